// round 5
// baseline (speedup 1.0000x reference)
#include <cuda_runtime.h>

// Shapes fixed by reference setup_inputs()
#define BB      16
#define NPTS    1024          // H*W
#define DD      128           // = 32 float4 chunks
#define KK      32
#define GPB     32            // chunks (CTAs) per batch
#define PPB     (NPTS / GPB)  // 32 points per CTA
#define NTHREADS 256
#define NCHUNK  (BB * GPB)    // 512

// Shared layout: xs[32][33] f4 | cs[32][34] f4 | As[32][33] f | x2s[32] f
#define XS_STRIDE 33
#define CS_STRIDE 34
#define AS_STRIDE 33
#define XS_BYTES  (PPB * XS_STRIDE * 16)            // 16896
#define CS_BYTES  (KK * CS_STRIDE * 16)             // 17408
#define AS_BYTES  (PPB * AS_STRIDE * 4)             // 4224
#define SMEM_BYTES (XS_BYTES + CS_BYTES + AS_BYTES + PPB * 4)  // 38656

// Cross-CTA partial tiles: [chunk][d][k] (coalesced STG over k; reduce loads float4 over k)
__device__ float4 g_Ep4[NCHUNK * KK * DD / 4];      // 8 MB scratch

__device__ __forceinline__ unsigned long long ffma2_(unsigned long long a,
                                                     unsigned long long b,
                                                     unsigned long long c) {
    unsigned long long d;
    asm("fma.rn.f32x2 %0, %1, %2, %3;" : "=l"(d) : "l"(a), "l"(b), "l"(c));
    return d;
}
__device__ __forceinline__ unsigned long long pack2(float lo, float hi) {
    unsigned long long r;
    asm("mov.b64 %0, {%1, %2};" : "=l"(r) : "f"(lo), "f"(hi));
    return r;
}
__device__ __forceinline__ float2 unpack2(unsigned long long v) {
    float2 r;
    asm("mov.b64 {%0, %1}, %2;" : "=f"(r.x), "=f"(r.y) : "l"(v));
    return r;
}

__global__ __launch_bounds__(NTHREADS, 3)
void ev_encode_kernel(const float* __restrict__ x,
                      const float* __restrict__ cw,
                      const float* __restrict__ scale) {
    extern __shared__ char sraw[];
    float4* xs  = (float4*)sraw;                          // [PPB][33]
    float4* cs  = (float4*)(sraw + XS_BYTES);             // [KK][34] rotated
    float*  As  = (float*)(sraw + XS_BYTES + CS_BYTES);   // [PPB][33]
    float*  x2s = As + PPB * AS_STRIDE;                   // [PPB]

    const int t    = threadIdx.x;
    const int lane = t & 31;
    const int w    = t >> 5;              // 0..7
    const int b    = blockIdx.x >> 5;
    const int g    = blockIdx.x & 31;
    const int mi   = lane & 1;            // point-subgroup (2 x 2 pts)
    const int ni   = lane >> 1;           // k-pair index (16 pairs)

    // ---- Phase A1: stage x tile; warp w loads rows w, w+8, w+16, w+24;
    //      chunk = lane -> fold ||x||^2 reduction into the staging pass ----
    const float4* xg = (const float4*)(x + ((size_t)b * NPTS + (size_t)g * PPB) * DD);
    #pragma unroll
    for (int i = 0; i < 4; ++i) {
        int p = w + 8 * i;
        float4 v = xg[p * 32 + lane];
        xs[p * XS_STRIDE + lane] = v;
        float s2 = v.x * v.x + v.y * v.y + v.z * v.z + v.w * v.w;
        #pragma unroll
        for (int o = 16; o; o >>= 1) s2 += __shfl_xor_sync(0xffffffffu, s2, o);
        if (lane == 0) x2s[p] = s2;
    }

    // ---- Phase A2: augmented codewords w_k = -2*s_k*c_k at slot (d4 + k/2)&31;
    //      slot 32 = (s_k, s_k*||c_k||^2, 0, 0). Warp w builds rows 4w..4w+3. ----
    #pragma unroll
    for (int j = 0; j < 4; ++j) {
        int k = w * 4 + j;
        float4 c = ((const float4*)cw)[k * 32 + lane];
        float s  = scale[k];
        float c2 = c.x * c.x + c.y * c.y + c.z * c.z + c.w * c.w;
        #pragma unroll
        for (int o = 16; o; o >>= 1) c2 += __shfl_xor_sync(0xffffffffu, c2, o);
        float m2 = -2.f * s;
        cs[k * CS_STRIDE + ((lane + (k >> 1)) & 31)] =
            make_float4(m2 * c.x, m2 * c.y, m2 * c.z, m2 * c.w);
        if (lane == 0)
            cs[k * CS_STRIDE + 32] = make_float4(s, s * c2, 0.f, 0.f);
    }
    __syncthreads();

    // ---- Phase C: stage-1 GEMM (logits), 2 pts x 2 k per lane ----
    unsigned long long acc[2][2];
    acc[0][0] = 0ull; acc[0][1] = 0ull; acc[1][0] = 0ull; acc[1][1] = 0ull;

    const int pbase = w * 4 + mi * 2;
    const ulonglong2* xs2 = (const ulonglong2*)xs;
    const ulonglong2* csrow0 = (const ulonglong2*)cs + (2 * ni + 0) * CS_STRIDE;
    const ulonglong2* csrow1 = (const ulonglong2*)cs + (2 * ni + 1) * CS_STRIDE;

    #pragma unroll 8
    for (int d4 = 0; d4 < 32; ++d4) {
        int cslot = (d4 + ni) & 31;
        ulonglong2 cv0 = csrow0[cslot];
        ulonglong2 cv1 = csrow1[cslot];
        #pragma unroll
        for (int p = 0; p < 2; ++p) {
            ulonglong2 xv = xs2[(pbase + p) * XS_STRIDE + d4];   // linear in d4
            acc[p][0] = ffma2_(cv0.x, xv.x, acc[p][0]);
            acc[p][0] = ffma2_(cv0.y, xv.y, acc[p][0]);
            acc[p][1] = ffma2_(cv1.x, xv.x, acc[p][1]);
            acc[p][1] = ffma2_(cv1.y, xv.y, acc[p][1]);
        }
    }

    float4 cc0 = cs[(2 * ni + 0) * CS_STRIDE + 32];   // (s, s*c2, 0, 0)
    float4 cc1 = cs[(2 * ni + 1) * CS_STRIDE + 32];

    // ---- softmax over K=32 (butterfly on ni bits; mi bit untouched) ----
    #pragma unroll
    for (int p = 0; p < 2; ++p) {
        float x2 = x2s[pbase + p];                     // broadcast LDS
        float2 u0 = unpack2(acc[p][0]);
        float2 u1 = unpack2(acc[p][1]);
        float SL0 = (u0.x + u0.y) + fmaf(cc0.x, x2, cc0.y);
        float SL1 = (u1.x + u1.y) + fmaf(cc1.x, x2, cc1.y);
        float m = fmaxf(SL0, SL1);
        #pragma unroll
        for (int o = 2; o <= 16; o <<= 1) m = fmaxf(m, __shfl_xor_sync(0xffffffffu, m, o));
        float e0 = __expf(SL0 - m);
        float e1 = __expf(SL1 - m);
        float ssum = e0 + e1;
        #pragma unroll
        for (int o = 2; o <= 16; o <<= 1) ssum += __shfl_xor_sync(0xffffffffu, ssum, o);
        float inv = 1.f / ssum;
        As[(pbase + p) * AS_STRIDE + 2 * ni + 0] = e0 * inv;
        As[(pbase + p) * AS_STRIDE + 2 * ni + 1] = e1 * inv;
    }
    __syncthreads();

    // ---- Phase D: E[k][d] = sum_p A[p][k]*x[p][d]; lane=k, warp owns 16 d ----
    unsigned long long acc2[8];
    #pragma unroll
    for (int q = 0; q < 8; ++q) acc2[q] = 0ull;
    float sA = 0.f;
    const int d4b = w * 4;

    #pragma unroll 8
    for (int p = 0; p < PPB; ++p) {
        float a = As[p * AS_STRIDE + lane];            // conflict-free (stride 33)
        sA += a;
        unsigned long long a2 = pack2(a, a);
        #pragma unroll
        for (int q = 0; q < 4; ++q) {
            ulonglong2 xv = xs2[p * XS_STRIDE + d4b + q];   // uniform -> broadcast
            acc2[2 * q + 0] = ffma2_(a2, xv.x, acc2[2 * q + 0]);
            acc2[2 * q + 1] = ffma2_(a2, xv.y, acc2[2 * q + 1]);
        }
    }

    // ---- epilogue: partial tile -> g_Ep[chunk][d][k], coalesced STG.32 over k ----
    float* ep = (float*)g_Ep4 + (size_t)blockIdx.x * (KK * DD);
    const float4* crow = (const float4*)(cw + (size_t)lane * DD);
    #pragma unroll
    for (int q = 0; q < 4; ++q) {
        int d4 = d4b + q;
        float4 c = crow[d4];
        float2 lo = unpack2(acc2[2 * q + 0]);
        float2 hi = unpack2(acc2[2 * q + 1]);
        ep[(4 * d4 + 0) * KK + lane] = fmaf(-sA, c.x, lo.x);
        ep[(4 * d4 + 1) * KK + lane] = fmaf(-sA, c.y, lo.y);
        ep[(4 * d4 + 2) * KK + lane] = fmaf(-sA, c.z, hi.x);
        ep[(4 * d4 + 3) * KK + lane] = fmaf(-sA, c.w, hi.y);
    }
}

// out[b][k][d] = sum_{c=0..31} g_Ep[b*32+c][d][k]; float4 over k, MLP=32
__global__ __launch_bounds__(128)
void ev_reduce_kernel(float* __restrict__ out) {
    int idx = blockIdx.x * 128 + threadIdx.x;     // 0..16383
    int k4 = idx & 7;                              // float4 group in k
    int d  = (idx >> 3) & 127;
    int b  = idx >> 10;
    const float4* base = g_Ep4 + ((size_t)b * GPB) * (KK * DD / 4)
                       + (size_t)d * (KK / 4) + k4;
    float4 s = make_float4(0.f, 0.f, 0.f, 0.f);
    #pragma unroll 8
    for (int c = 0; c < GPB; ++c) {
        float4 v = base[(size_t)c * (KK * DD / 4)];   // coalesced 512B/warp
        s.x += v.x; s.y += v.y; s.z += v.z; s.w += v.w;
    }
    float* ob = out + ((size_t)b * KK + 4 * k4) * DD + d;
    ob[0 * DD] = s.x;
    ob[1 * DD] = s.y;
    ob[2 * DD] = s.z;
    ob[3 * DD] = s.w;
}

extern "C" void kernel_launch(void* const* d_in, const int* in_sizes, int n_in,
                              void* d_out, int out_size) {
    const float* x  = (const float*)d_in[0];   // [16,32,32,128]
    const float* cw = (const float*)d_in[1];   // [32,128]
    const float* sc = (const float*)d_in[2];   // [32]
    float* out = (float*)d_out;                // [16,32,128]

    cudaFuncSetAttribute(ev_encode_kernel,
                         cudaFuncAttributeMaxDynamicSharedMemorySize, SMEM_BYTES);

    ev_encode_kernel<<<NCHUNK, NTHREADS, SMEM_BYTES>>>(x, cw, sc);
    ev_reduce_kernel<<<(BB * KK * DD / 4) / 128, 128>>>(out);
}